// round 2
// baseline (speedup 1.0000x reference)
#include <cuda_runtime.h>
#include <math.h>
#include <stdint.h>

#define BB 16
#define CC 512
#define NN 2304
#define NTILES 36   // NN / 64

// Scratch (allocation-free rule: __device__ globals)
__device__ float g_flat[(size_t)BB * CC * NN];   // tf32-rounded normalized x, [b][c][n]
__device__ float g_att[BB * NN];
__device__ float g_refine[BB * NN];

__device__ __forceinline__ float tf32_round(float x) {
    unsigned u;
    asm("cvt.rna.tf32.f32 %0, %1;" : "=r"(u) : "f"(x));
    return __uint_as_float(u);
}

// ---------------------------------------------------------------------------
// Kernel 1: per (b,n): att = softplus(x·wq), norm over c, write flat, zero refine
// ---------------------------------------------------------------------------
__global__ void __launch_bounds__(256) prep_kernel(const float* __restrict__ x,
                                                   const float* __restrict__ wq) {
    __shared__ float swq[CC];
    int tid = threadIdx.x;
    for (int i = tid; i < CC; i += 256) swq[i] = wq[i];
    __syncthreads();

    int gid = blockIdx.x * 256 + tid;     // 0 .. BB*NN-1 (exact)
    int b = gid / NN;
    int n = gid - b * NN;
    const float* xb = x + (size_t)b * CC * NN + n;

    float ss = 0.f, dot = 0.f;
    #pragma unroll 8
    for (int c = 0; c < CC; c++) {
        float v = xb[(size_t)c * NN];
        ss  = fmaf(v, v, ss);
        dot = fmaf(v, swq[c], dot);
    }
    float inv = 1.0f / fmaxf(sqrtf(ss), 1e-12f);

    // softplus, overflow-safe
    float att = (dot > 20.0f) ? dot : log1pf(expf(dot));
    g_att[b * NN + n]    = att;
    g_refine[b * NN + n] = 0.0f;

    float* fb = g_flat + (size_t)b * CC * NN + n;
    #pragma unroll 8
    for (int c = 0; c < CC; c++) {
        float v = xb[(size_t)c * NN];
        fb[(size_t)c * NN] = tf32_round(v * inv);
    }
}

// ---------------------------------------------------------------------------
// Kernel 2: per (b, rTile, qTile): S = F[:,r]ᵀ F[:,q] (64x64 over K=512, tf32 mma)
//           epilogue: refine[r] += sum_q relu(S)^2 * att[q]   (atomicAdd)
// ---------------------------------------------------------------------------
#define BK 16
#define SPAD 72   // row stride (72 % 32 = 8 -> conflict-free fragment loads)

__device__ __forceinline__ void mma_tf32(float c[4], const uint32_t a[4], const uint32_t b[2]) {
    asm("mma.sync.aligned.m16n8k8.row.col.f32.tf32.tf32.f32 "
        "{%0,%1,%2,%3}, {%4,%5,%6,%7}, {%8,%9}, {%0,%1,%2,%3};"
        : "+f"(c[0]), "+f"(c[1]), "+f"(c[2]), "+f"(c[3])
        : "r"(a[0]), "r"(a[1]), "r"(a[2]), "r"(a[3]), "r"(b[0]), "r"(b[1]));
}

__global__ void __launch_bounds__(128) gemm_refine_kernel() {
    __shared__ float As[BK][SPAD];
    __shared__ float Bs[BK][SPAD];
    __shared__ float atts[64];

    int b    = blockIdx.z;
    int rblk = blockIdx.y * 64;   // refine-row tile (n index)
    int qblk = blockIdx.x * 64;   // att-col tile (m index)

    int tid  = threadIdx.x;
    int lane = tid & 31;
    int w    = tid >> 5;
    int warpR = (w >> 1) * 32;    // warp row offset within block tile
    int warpQ = (w & 1) * 32;     // warp col offset

    const float* F = g_flat + (size_t)b * CC * NN;
    if (tid < 64) atts[tid] = g_att[b * NN + qblk + tid];

    float acc[2][4][4];
    #pragma unroll
    for (int mi = 0; mi < 2; mi++)
        #pragma unroll
        for (int ni = 0; ni < 4; ni++)
            #pragma unroll
            for (int k = 0; k < 4; k++) acc[mi][ni][k] = 0.f;

    // gmem->smem load mapping: 128 threads, each 2 rows x float4
    int lr = tid >> 4;           // 0..7
    int lc = (tid & 15) * 4;     // 0..60

    for (int kb = 0; kb < CC; kb += BK) {
        #pragma unroll
        for (int i = 0; i < 2; i++) {
            int row = lr + i * 8;
            const float4 va = *(const float4*)(F + (size_t)(kb + row) * NN + rblk + lc);
            *(float4*)&As[row][lc] = va;
            const float4 vb = *(const float4*)(F + (size_t)(kb + row) * NN + qblk + lc);
            *(float4*)&Bs[row][lc] = vb;
        }
        __syncthreads();

        #pragma unroll
        for (int ks = 0; ks < BK; ks += 8) {
            uint32_t afr[2][4], bfr[4][2];
            int tg = lane & 3;       // threadID_in_group
            int gp = lane >> 2;      // groupID
            #pragma unroll
            for (int mi = 0; mi < 2; mi++) {
                int n0 = warpR + mi * 16;
                afr[mi][0] = __float_as_uint(As[ks + tg    ][n0 + gp    ]);
                afr[mi][1] = __float_as_uint(As[ks + tg    ][n0 + gp + 8]);
                afr[mi][2] = __float_as_uint(As[ks + tg + 4][n0 + gp    ]);
                afr[mi][3] = __float_as_uint(As[ks + tg + 4][n0 + gp + 8]);
            }
            #pragma unroll
            for (int ni = 0; ni < 4; ni++) {
                int m0 = warpQ + ni * 8;
                bfr[ni][0] = __float_as_uint(Bs[ks + tg    ][m0 + gp]);
                bfr[ni][1] = __float_as_uint(Bs[ks + tg + 4][m0 + gp]);
            }
            #pragma unroll
            for (int mi = 0; mi < 2; mi++)
                #pragma unroll
                for (int ni = 0; ni < 4; ni++)
                    mma_tf32(acc[mi][ni], afr[mi], bfr[ni]);
        }
        __syncthreads();
    }

    // Epilogue: relu^2 * att, row-sum, reduce over quad, atomicAdd
    int tg = lane & 3;
    int gp = lane >> 2;
    #pragma unroll
    for (int mi = 0; mi < 2; mi++) {
        float rlo = 0.f, rhi = 0.f;
        #pragma unroll
        for (int ni = 0; ni < 4; ni++) {
            int q0 = warpQ + ni * 8 + tg * 2;
            float w0 = atts[q0], w1 = atts[q0 + 1];
            float s;
            s = fmaxf(acc[mi][ni][0], 0.f); rlo = fmaf(s * s, w0, rlo);
            s = fmaxf(acc[mi][ni][1], 0.f); rlo = fmaf(s * s, w1, rlo);
            s = fmaxf(acc[mi][ni][2], 0.f); rhi = fmaf(s * s, w0, rhi);
            s = fmaxf(acc[mi][ni][3], 0.f); rhi = fmaf(s * s, w1, rhi);
        }
        rlo += __shfl_xor_sync(0xffffffffu, rlo, 1);
        rlo += __shfl_xor_sync(0xffffffffu, rlo, 2);
        rhi += __shfl_xor_sync(0xffffffffu, rhi, 1);
        rhi += __shfl_xor_sync(0xffffffffu, rhi, 2);
        if (tg == 0) {
            int r0 = rblk + warpR + mi * 16 + gp;
            atomicAdd(&g_refine[b * NN + r0],     rlo);
            atomicAdd(&g_refine[b * NN + r0 + 8], rhi);
        }
    }
}

// ---------------------------------------------------------------------------
// Kernel 3: out[b][c] = mean_n x[b][c][n] * refine[b][n]
// ---------------------------------------------------------------------------
__global__ void __launch_bounds__(256) out_kernel(const float* __restrict__ x,
                                                  float* __restrict__ out) {
    int bc = blockIdx.x;          // b*CC + c
    int b = bc / CC;
    const float* xr = x + (size_t)bc * NN;
    const float* rf = g_refine + b * NN;

    float s = 0.f;
    for (int n = threadIdx.x; n < NN; n += 256) s = fmaf(xr[n], rf[n], s);

    __shared__ float red[256];
    red[threadIdx.x] = s;
    __syncthreads();
    for (int off = 128; off > 0; off >>= 1) {
        if (threadIdx.x < off) red[threadIdx.x] += red[threadIdx.x + off];
        __syncthreads();
    }
    if (threadIdx.x == 0) out[bc] = red[0] * (1.0f / (float)NN);
}

// ---------------------------------------------------------------------------
extern "C" void kernel_launch(void* const* d_in, const int* in_sizes, int n_in,
                              void* d_out, int out_size) {
    const float* x  = (const float*)d_in[0];   // [16, 512, 48, 48]
    const float* wq = (const float*)d_in[1];   // [512]
    float* out = (float*)d_out;                // [16, 512, 1, 1]

    prep_kernel<<<(BB * NN) / 256, 256>>>(x, wq);
    gemm_refine_kernel<<<dim3(NTILES, NTILES, BB), 128>>>();
    out_kernel<<<BB * CC, 256>>>(x, out);
}

// round 7
// speedup vs baseline: 1.9692x; 1.9692x over previous
#include <cuda_runtime.h>
#include <math.h>
#include <stdint.h>

#define BB 16
#define CC 512
#define NN 2304
#define NT 18            // NN / 128 tiles
#define NPAIRS 171       // NT*(NT+1)/2

// ---------------- scratch (__device__ globals; no allocs allowed) -----------
__device__ float g_xn[(size_t)BB * CC * NN];   // tf32-rounded normalized x, [b][c][n]
__device__ float g_att[BB * NN];
__device__ float g_refine[BB * NN];

__device__ __forceinline__ uint32_t smem_u32(const void* p) {
    uint32_t a;
    asm("{ .reg .u64 t; cvta.to.shared.u64 t, %1; cvt.u32.u64 %0, t; }" : "=r"(a) : "l"(p));
    return a;
}
__device__ __forceinline__ float tf32_round(float x) {
    unsigned u;
    asm("cvt.rna.tf32.f32 %0, %1;" : "=r"(u) : "f"(x));
    return __uint_as_float(u);
}
__device__ __forceinline__ void cp_async16(uint32_t dst, const void* src) {
    asm volatile("cp.async.cg.shared.global [%0], [%1], 16;" :: "r"(dst), "l"(src) : "memory");
}
#define CP_COMMIT() asm volatile("cp.async.commit_group;" ::: "memory")

__device__ __forceinline__ void mma_tf32(float c[4], const uint32_t a[4], const uint32_t b[2]) {
    asm("mma.sync.aligned.m16n8k8.row.col.f32.tf32.tf32.f32 "
        "{%0,%1,%2,%3}, {%4,%5,%6,%7}, {%8,%9}, {%0,%1,%2,%3};"
        : "+f"(c[0]), "+f"(c[1]), "+f"(c[2]), "+f"(c[3])
        : "r"(a[0]), "r"(a[1]), "r"(a[2]), "r"(a[3]), "r"(b[0]), "r"(b[1]));
}

// ---------------------------------------------------------------------------
// prep: per (b,n): ss & dot over c -> att, inv; then write g_xn = rna(x*inv)
// block = 64 n-positions x 4 c-slices (256 threads); grid = BB * NN/64 = 576
// ---------------------------------------------------------------------------
__global__ void __launch_bounds__(256) prep_kernel(const float* __restrict__ x,
                                                   const float* __restrict__ wq) {
    __shared__ float swq[CC];
    __shared__ float s_ss[256], s_dot[256];
    __shared__ float s_inv[64];

    int tid = threadIdx.x;
    for (int i = tid; i < CC; i += 256) swq[i] = wq[i];
    __syncthreads();

    int b  = blockIdx.x / (NN / 64);
    int nt = blockIdx.x % (NN / 64);
    int cs = tid >> 6;          // c-slice 0..3
    int nl = tid & 63;
    int n  = nt * 64 + nl;

    const float* xb = x + ((size_t)b * CC + cs * 128) * NN + n;
    const float* wp = swq + cs * 128;

    float ss = 0.f, dot = 0.f;
    #pragma unroll 8
    for (int c = 0; c < 128; c++) {
        float v = xb[(size_t)c * NN];
        ss  = fmaf(v, v, ss);
        dot = fmaf(v, wp[c], dot);
    }
    s_ss[tid] = ss; s_dot[tid] = dot;
    __syncthreads();

    if (tid < 64) {
        float tss = s_ss[tid] + s_ss[tid + 64] + s_ss[tid + 128] + s_ss[tid + 192];
        float td  = s_dot[tid] + s_dot[tid + 64] + s_dot[tid + 128] + s_dot[tid + 192];
        float inv = 1.0f / fmaxf(sqrtf(tss), 1e-12f);
        s_inv[tid] = inv;
        int gid = b * NN + nt * 64 + tid;
        g_att[gid]    = (td > 20.0f) ? td : log1pf(expf(td));
        g_refine[gid] = 0.0f;
    }
    __syncthreads();

    // second pass: L1/L2-hot re-read, write rounded normalized values
    float inv = s_inv[nl];
    float* ob = g_xn + ((size_t)b * CC + cs * 128) * NN + n;
    #pragma unroll 8
    for (int c = 0; c < 128; c++) {
        float v = xb[(size_t)c * NN];
        ob[(size_t)c * NN] = tf32_round(v * inv);
    }
}

// ---------------------------------------------------------------------------
// gemm: per (b, tile-pair i<=j): S = Xn_i^T Xn_j over K=512 (tf32 mma.sync)
//   epilogue: p = relu(S)^2
//   refine[rows_i] += sum_cols p*attQ; if i<j: refine[cols_j] += sum_rows p*attR
// ---------------------------------------------------------------------------
#define BK 16
#define LDPAD 132   // floats per smem row (128 + 4 pad)

__global__ void __launch_bounds__(256) gemm_kernel() {
    __shared__ float As[2][BK][LDPAD];
    __shared__ float Bs[2][BK][LDPAD];
    __shared__ float srow[128], scol[128];
    __shared__ float attR[128], attQ[128];

    int b    = blockIdx.y;
    int pair = blockIdx.x;
    // decode pair -> (i, j), i <= j
    int i = 0, rem = pair;
    while (rem >= NT - i) { rem -= NT - i; i++; }
    int j = i + rem;
    int rblk = i * 128;
    int qblk = j * 128;
    bool diag = (i == j);

    int tid  = threadIdx.x;
    int lane = tid & 31;
    int wid  = tid >> 5;
    int warpR = (wid >> 1) * 32;  // 4 warp-rows
    int warpQ = (wid & 1) * 64;   // 2 warp-cols

    if (tid < 128) {
        attR[tid] = g_att[b * NN + rblk + tid];
        attQ[tid] = g_att[b * NN + qblk + tid];
        srow[tid] = 0.f; scol[tid] = 0.f;
    }

    const float* xb = g_xn + (size_t)b * CC * NN;
    uint32_t as_base = smem_u32(&As[0][0][0]);
    uint32_t bs_base = smem_u32(&Bs[0][0][0]);

    // load one BK-stage: 2 tiles x 16 rows x 128 floats = 1024 16B granules
    auto load_stage = [&](int round, int stg) {
        int kof = round * BK;
        uint32_t soff = (uint32_t)stg * (BK * LDPAD * 4);
        #pragma unroll
        for (int it = 0; it < 4; it++) {
            int g = tid + it * 256;
            int tsel = g >> 9;            // 0 = A, 1 = B
            int r    = (g >> 5) & 15;
            int c16  = g & 31;
            const float* src = xb + (size_t)(kof + r) * NN +
                               (tsel ? qblk : rblk) + c16 * 4;
            uint32_t dst = (tsel ? bs_base : as_base) + soff + r * (LDPAD * 4) + c16 * 16;
            cp_async16(dst, src);
        }
        CP_COMMIT();
    };

    float acc[2][8][4];
    #pragma unroll
    for (int mi = 0; mi < 2; mi++)
        #pragma unroll
        for (int ni = 0; ni < 8; ni++)
            #pragma unroll
            for (int k = 0; k < 4; k++) acc[mi][ni][k] = 0.f;

    load_stage(0, 0);

    const int ROUNDS = CC / BK;   // 32
    int tg = lane & 3;
    int gp = lane >> 2;

    for (int kb = 0; kb < ROUNDS; kb++) {
        int cs = kb & 1;
        if (kb + 1 < ROUNDS) {
            load_stage(kb + 1, (kb + 1) & 1);
            asm volatile("cp.async.wait_group 1;" ::: "memory");
        } else {
            asm volatile("cp.async.wait_group 0;" ::: "memory");
        }
        __syncthreads();

        #pragma unroll
        for (int ks = 0; ks < BK; ks += 8) {
            uint32_t afr[2][4], bfr[8][2];
            #pragma unroll
            for (int mi = 0; mi < 2; mi++) {
                int n0 = warpR + mi * 16;
                afr[mi][0] = __float_as_uint(As[cs][ks + tg    ][n0 + gp    ]);
                afr[mi][1] = __float_as_uint(As[cs][ks + tg    ][n0 + gp + 8]);
                afr[mi][2] = __float_as_uint(As[cs][ks + tg + 4][n0 + gp    ]);
                afr[mi][3] = __float_as_uint(As[cs][ks + tg + 4][n0 + gp + 8]);
            }
            #pragma unroll
            for (int ni = 0; ni < 8; ni++) {
                int m0 = warpQ + ni * 8;
                bfr[ni][0] = __float_as_uint(Bs[cs][ks + tg    ][m0 + gp]);
                bfr[ni][1] = __float_as_uint(Bs[cs][ks + tg + 4][m0 + gp]);
            }
            #pragma unroll
            for (int mi = 0; mi < 2; mi++)
                #pragma unroll
                for (int ni = 0; ni < 8; ni++)
                    mma_tf32(acc[mi][ni], afr[mi], bfr[ni]);
        }
        __syncthreads();
    }

    // ----- epilogue -----
    float csum[8][2];
    #pragma unroll
    for (int ni = 0; ni < 8; ni++) { csum[ni][0] = 0.f; csum[ni][1] = 0.f; }

    #pragma unroll
    for (int mi = 0; mi < 2; mi++) {
        int r0 = warpR + mi * 16 + gp;
        int r1 = r0 + 8;
        float ar0 = attR[r0], ar1 = attR[r1];
        float rlo = 0.f, rhi = 0.f;
        #pragma unroll
        for (int ni = 0; ni < 8; ni++) {
            int c0 = warpQ + ni * 8 + tg * 2;
            int c1 = c0 + 1;
            float aq0 = attQ[c0], aq1 = attQ[c1];
            float s, p;
            s = fmaxf(acc[mi][ni][0], 0.f); p = s * s;
            rlo = fmaf(p, aq0, rlo); csum[ni][0] = fmaf(p, ar0, csum[ni][0]);
            s = fmaxf(acc[mi][ni][1], 0.f); p = s * s;
            rlo = fmaf(p, aq1, rlo); csum[ni][1] = fmaf(p, ar0, csum[ni][1]);
            s = fmaxf(acc[mi][ni][2], 0.f); p = s * s;
            rhi = fmaf(p, aq0, rhi); csum[ni][0] = fmaf(p, ar1, csum[ni][0]);
            s = fmaxf(acc[mi][ni][3], 0.f); p = s * s;
            rhi = fmaf(p, aq1, rhi); csum[ni][1] = fmaf(p, ar1, csum[ni][1]);
        }
        // reduce rows over tg (lane bits 1,2)
        rlo += __shfl_xor_sync(0xffffffffu, rlo, 1);
        rlo += __shfl_xor_sync(0xffffffffu, rlo, 2);
        rhi += __shfl_xor_sync(0xffffffffu, rhi, 1);
        rhi += __shfl_xor_sync(0xffffffffu, rhi, 2);
        if (tg == 0) {
            atomicAdd(&srow[r0], rlo);
            atomicAdd(&srow[r1], rhi);
        }
    }
    if (!diag) {
        // reduce cols over gp (lane bits 4,8,16)
        #pragma unroll
        for (int ni = 0; ni < 8; ni++) {
            float c0v = csum[ni][0], c1v = csum[ni][1];
            c0v += __shfl_xor_sync(0xffffffffu, c0v, 4);
            c0v += __shfl_xor_sync(0xffffffffu, c0v, 8);
            c0v += __shfl_xor_sync(0xffffffffu, c0v, 16);
            c1v += __shfl_xor_sync(0xffffffffu, c1v, 4);
            c1v += __shfl_xor_sync(0xffffffffu, c1v, 8);
            c1v += __shfl_xor_sync(0xffffffffu, c1v, 16);
            if (gp == 0) {
                int c0 = warpQ + ni * 8 + tg * 2;
                atomicAdd(&scol[c0],     c0v);
                atomicAdd(&scol[c0 + 1], c1v);
            }
        }
    }
    __syncthreads();

    if (tid < 128) {
        atomicAdd(&g_refine[b * NN + rblk + tid], srow[tid]);
        if (!diag) atomicAdd(&g_refine[b * NN + qblk + tid], scol[tid]);
    }
}

// ---------------------------------------------------------------------------
// out: out[b][c] = mean_n x[b][c][n] * refine[b][n]
// ---------------------------------------------------------------------------
__global__ void __launch_bounds__(256) out_kernel(const float* __restrict__ x,
                                                  float* __restrict__ out) {
    int bc = blockIdx.x;
    int b = bc / CC;
    const float4* xr = (const float4*)(x + (size_t)bc * NN);
    const float4* rf = (const float4*)(g_refine + b * NN);

    float s = 0.f;
    for (int q = threadIdx.x; q < NN / 4; q += 256) {
        float4 xv = xr[q];
        float4 rv = rf[q];
        s = fmaf(xv.x, rv.x, s);
        s = fmaf(xv.y, rv.y, s);
        s = fmaf(xv.z, rv.z, s);
        s = fmaf(xv.w, rv.w, s);
    }

    __shared__ float red[256];
    red[threadIdx.x] = s;
    __syncthreads();
    for (int off = 128; off > 0; off >>= 1) {
        if (threadIdx.x < off) red[threadIdx.x] += red[threadIdx.x + off];
        __syncthreads();
    }
    if (threadIdx.x == 0) out[bc] = red[0] * (1.0f / (float)NN);
}

// ---------------------------------------------------------------------------
extern "C" void kernel_launch(void* const* d_in, const int* in_sizes, int n_in,
                              void* d_out, int out_size) {
    const float* x  = (const float*)d_in[0];   // [16, 512, 48, 48]
    const float* wq = (const float*)d_in[1];   // [512]
    float* out = (float*)d_out;                // [16, 512, 1, 1]

    prep_kernel<<<BB * (NN / 64), 256>>>(x, wq);
    gemm_kernel<<<dim3(NPAIRS, BB), 256>>>();
    out_kernel<<<BB * CC, 256>>>(x, out);
}

// round 8
// speedup vs baseline: 2.8564x; 1.4506x over previous
#include <cuda_runtime.h>
#include <cuda_fp16.h>
#include <math.h>
#include <stdint.h>

#define BB 16
#define CC 512
#define NN 2304
#define NT 18            // NN / 128 tiles
#define NPAIRS 171       // NT*(NT+1)/2

// ---------------- scratch (__device__ globals; no allocs allowed) -----------
__device__ __half g_xn[(size_t)BB * NN * CC];   // fp16-RN normalized x, [b][n][c]
__device__ float g_att[BB * NN];
__device__ float g_refine[BB * NN];

__device__ __forceinline__ uint32_t smem_u32(const void* p) {
    uint32_t a;
    asm("{ .reg .u64 t; cvta.to.shared.u64 t, %1; cvt.u32.u64 %0, t; }" : "=r"(a) : "l"(p));
    return a;
}
__device__ __forceinline__ void cp_async16(uint32_t dst, const void* src) {
    asm volatile("cp.async.cg.shared.global [%0], [%1], 16;" :: "r"(dst), "l"(src) : "memory");
}
#define CP_COMMIT() asm volatile("cp.async.commit_group;" ::: "memory")

__device__ __forceinline__ void mma_f16(float c[4], const uint32_t a[4], const uint32_t b[2]) {
    asm("mma.sync.aligned.m16n8k16.row.col.f32.f16.f16.f32 "
        "{%0,%1,%2,%3}, {%4,%5,%6,%7}, {%8,%9}, {%0,%1,%2,%3};"
        : "+f"(c[0]), "+f"(c[1]), "+f"(c[2]), "+f"(c[3])
        : "r"(a[0]), "r"(a[1]), "r"(a[2]), "r"(a[3]), "r"(b[0]), "r"(b[1]));
}

// ---------------------------------------------------------------------------
// prep: block = 64 n x full C. Phase1: ss/dot -> inv, att. Phase2: transposed
// fp16 write g_xn[b][n][c] = rn(x * inv) via 64x64 smem tiles.
// grid = BB * NN/64 = 576
// ---------------------------------------------------------------------------
__global__ void __launch_bounds__(256) prep_kernel(const float* __restrict__ x,
                                                   const float* __restrict__ wq) {
    __shared__ float swq[CC];
    __shared__ float s_ss[256], s_dot[256];
    __shared__ float s_inv[64];
    __shared__ float tile[64][65];

    int tid = threadIdx.x;
    for (int i = tid; i < CC; i += 256) swq[i] = wq[i];
    __syncthreads();

    int b  = blockIdx.x / (NN / 64);
    int nt = blockIdx.x % (NN / 64);
    int n0 = nt * 64;
    int cs = tid >> 6;          // c-slice 0..3
    int nl = tid & 63;

    const float* xb0 = x + (size_t)b * CC * NN;
    const float* xb  = xb0 + (size_t)(cs * 128) * NN + n0 + nl;
    const float* wp  = swq + cs * 128;

    float ss = 0.f, dot = 0.f;
    #pragma unroll 8
    for (int c = 0; c < 128; c++) {
        float v = xb[(size_t)c * NN];
        ss  = fmaf(v, v, ss);
        dot = fmaf(v, wp[c], dot);
    }
    s_ss[tid] = ss; s_dot[tid] = dot;
    __syncthreads();

    if (tid < 64) {
        float tss = s_ss[tid] + s_ss[tid + 64] + s_ss[tid + 128] + s_ss[tid + 192];
        float td  = s_dot[tid] + s_dot[tid + 64] + s_dot[tid + 128] + s_dot[tid + 192];
        s_inv[tid] = 1.0f / fmaxf(sqrtf(tss), 1e-12f);
        int gid = b * NN + n0 + tid;
        g_att[gid]    = (td > 20.0f) ? td : log1pf(expf(td));
        g_refine[gid] = 0.0f;
    }
    __syncthreads();

    // phase 2: transpose to [n][c], scale, fp16-RN
    __half* ob = g_xn + (size_t)b * NN * CC;
    for (int c0 = 0; c0 < CC; c0 += 64) {
        #pragma unroll
        for (int it = 0; it < 16; it++) {
            int e = tid + it * 256;
            int cc = e >> 6, nn = e & 63;
            tile[cc][nn] = xb0[(size_t)(c0 + cc) * NN + n0 + nn];
        }
        __syncthreads();
        #pragma unroll
        for (int it = 0; it < 16; it++) {
            int e = tid + it * 256;
            int nn = e >> 6, cc = e & 63;
            ob[(size_t)(n0 + nn) * CC + c0 + cc] =
                __float2half_rn(tile[cc][nn] * s_inv[nn]);
        }
        __syncthreads();
    }
}

// ---------------------------------------------------------------------------
// gemm: per (b, tile-pair i<=j): S = Xn_i Xn_j^T over K=512 (fp16 mma.sync)
//   epilogue: p = relu(S)^2
//   refine[rows_i] += sum_cols p*attQ; if i<j: refine[cols_j] += sum_rows p*attR
// smem tiles [n][k], row stride 40 halves (80B = 20 banks, conflict-free)
// ---------------------------------------------------------------------------
#define BK 32
#define ROWH 40                    // halves per smem row
#define STG_H (128 * ROWH)         // halves per tile-stage (5120)

__global__ void __launch_bounds__(256) gemm_kernel() {
    __shared__ __half As[2][128][ROWH];   // 20480 B
    __shared__ __half Bs[2][128][ROWH];   // 20480 B
    __shared__ float srow[128], scol[128];
    __shared__ float attR[128], attQ[128];

    int b    = blockIdx.y;
    int pair = blockIdx.x;
    int i = 0, rem = pair;
    while (rem >= NT - i) { rem -= NT - i; i++; }
    int j = i + rem;
    int rblk = i * 128;
    int qblk = j * 128;
    bool diag = (i == j);

    int tid  = threadIdx.x;
    int lane = tid & 31;
    int wid  = tid >> 5;
    int warpR = (wid >> 1) * 32;  // 4 warp-rows
    int warpQ = (wid & 1) * 64;   // 2 warp-cols

    if (tid < 128) {
        attR[tid] = g_att[b * NN + rblk + tid];
        attQ[tid] = g_att[b * NN + qblk + tid];
        srow[tid] = 0.f; scol[tid] = 0.f;
    }

    const __half* xb = g_xn + (size_t)b * NN * CC;
    uint32_t as_base = smem_u32(&As[0][0][0]);
    uint32_t bs_base = smem_u32(&Bs[0][0][0]);

    // stage load: 2 tiles x 128 rows x 4 granules(16B) = 1024 granules
    auto load_stage = [&](int round, int stg) {
        int kof = round * BK;
        #pragma unroll
        for (int it = 0; it < 4; it++) {
            int g = tid + it * 256;
            int tsel = g >> 9;
            int row  = (g >> 2) & 127;
            int c4   = g & 3;
            const __half* src = xb + (size_t)((tsel ? qblk : rblk) + row) * CC + kof + c4 * 8;
            uint32_t dst = (tsel ? bs_base : as_base) +
                           (uint32_t)stg * (STG_H * 2) + row * (ROWH * 2) + c4 * 16;
            cp_async16(dst, src);
        }
        CP_COMMIT();
    };

    float acc[2][8][4];
    #pragma unroll
    for (int mi = 0; mi < 2; mi++)
        #pragma unroll
        for (int ni = 0; ni < 8; ni++)
            #pragma unroll
            for (int k = 0; k < 4; k++) acc[mi][ni][k] = 0.f;

    load_stage(0, 0);

    const int ROUNDS = CC / BK;   // 16
    int tg = lane & 3;
    int gp = lane >> 2;

    for (int kb = 0; kb < ROUNDS; kb++) {
        int cs = kb & 1;
        if (kb + 1 < ROUNDS) {
            load_stage(kb + 1, (kb + 1) & 1);
            asm volatile("cp.async.wait_group 1;" ::: "memory");
        } else {
            asm volatile("cp.async.wait_group 0;" ::: "memory");
        }
        __syncthreads();

        #pragma unroll
        for (int ks = 0; ks < BK; ks += 16) {
            uint32_t afr[2][4], bfr[8][2];
            #pragma unroll
            for (int mi = 0; mi < 2; mi++) {
                int r0 = warpR + mi * 16 + gp;
                afr[mi][0] = *(const uint32_t*)&As[cs][r0    ][ks + tg * 2    ];
                afr[mi][1] = *(const uint32_t*)&As[cs][r0 + 8][ks + tg * 2    ];
                afr[mi][2] = *(const uint32_t*)&As[cs][r0    ][ks + tg * 2 + 8];
                afr[mi][3] = *(const uint32_t*)&As[cs][r0 + 8][ks + tg * 2 + 8];
            }
            #pragma unroll
            for (int ni = 0; ni < 8; ni++) {
                int c0 = warpQ + ni * 8 + gp;
                bfr[ni][0] = *(const uint32_t*)&Bs[cs][c0][ks + tg * 2    ];
                bfr[ni][1] = *(const uint32_t*)&Bs[cs][c0][ks + tg * 2 + 8];
            }
            #pragma unroll
            for (int mi = 0; mi < 2; mi++)
                #pragma unroll
                for (int ni = 0; ni < 8; ni++)
                    mma_f16(acc[mi][ni], afr[mi], bfr[ni]);
        }
        __syncthreads();
    }

    // ----- epilogue -----
    float csum[8][2];
    #pragma unroll
    for (int ni = 0; ni < 8; ni++) { csum[ni][0] = 0.f; csum[ni][1] = 0.f; }

    #pragma unroll
    for (int mi = 0; mi < 2; mi++) {
        int r0 = warpR + mi * 16 + gp;
        int r1 = r0 + 8;
        float ar0 = attR[r0], ar1 = attR[r1];
        float rlo = 0.f, rhi = 0.f;
        #pragma unroll
        for (int ni = 0; ni < 8; ni++) {
            int c0 = warpQ + ni * 8 + tg * 2;
            int c1 = c0 + 1;
            float aq0 = attQ[c0], aq1 = attQ[c1];
            float s, p;
            s = fmaxf(acc[mi][ni][0], 0.f); p = s * s;
            rlo = fmaf(p, aq0, rlo); csum[ni][0] = fmaf(p, ar0, csum[ni][0]);
            s = fmaxf(acc[mi][ni][1], 0.f); p = s * s;
            rlo = fmaf(p, aq1, rlo); csum[ni][1] = fmaf(p, ar0, csum[ni][1]);
            s = fmaxf(acc[mi][ni][2], 0.f); p = s * s;
            rhi = fmaf(p, aq0, rhi); csum[ni][0] = fmaf(p, ar1, csum[ni][0]);
            s = fmaxf(acc[mi][ni][3], 0.f); p = s * s;
            rhi = fmaf(p, aq1, rhi); csum[ni][1] = fmaf(p, ar1, csum[ni][1]);
        }
        rlo += __shfl_xor_sync(0xffffffffu, rlo, 1);
        rlo += __shfl_xor_sync(0xffffffffu, rlo, 2);
        rhi += __shfl_xor_sync(0xffffffffu, rhi, 1);
        rhi += __shfl_xor_sync(0xffffffffu, rhi, 2);
        if (tg == 0) {
            atomicAdd(&srow[r0], rlo);
            atomicAdd(&srow[r1], rhi);
        }
    }
    if (!diag) {
        #pragma unroll
        for (int ni = 0; ni < 8; ni++) {
            float c0v = csum[ni][0], c1v = csum[ni][1];
            c0v += __shfl_xor_sync(0xffffffffu, c0v, 4);
            c0v += __shfl_xor_sync(0xffffffffu, c0v, 8);
            c0v += __shfl_xor_sync(0xffffffffu, c0v, 16);
            c1v += __shfl_xor_sync(0xffffffffu, c1v, 4);
            c1v += __shfl_xor_sync(0xffffffffu, c1v, 8);
            c1v += __shfl_xor_sync(0xffffffffu, c1v, 16);
            if (gp == 0) {
                int c0 = warpQ + ni * 8 + tg * 2;
                atomicAdd(&scol[c0],     c0v);
                atomicAdd(&scol[c0 + 1], c1v);
            }
        }
    }
    __syncthreads();

    if (tid < 128) {
        atomicAdd(&g_refine[b * NN + rblk + tid], srow[tid]);
        if (!diag) atomicAdd(&g_refine[b * NN + qblk + tid], scol[tid]);
    }
}

// ---------------------------------------------------------------------------
// out: out[b][c] = mean_n x[b][c][n] * refine[b][n]
// ---------------------------------------------------------------------------
__global__ void __launch_bounds__(256) out_kernel(const float* __restrict__ x,
                                                  float* __restrict__ out) {
    int bc = blockIdx.x;
    int b = bc / CC;
    const float4* xr = (const float4*)(x + (size_t)bc * NN);
    const float4* rf = (const float4*)(g_refine + b * NN);

    float s = 0.f;
    for (int q = threadIdx.x; q < NN / 4; q += 256) {
        float4 xv = xr[q];
        float4 rv = rf[q];
        s = fmaf(xv.x, rv.x, s);
        s = fmaf(xv.y, rv.y, s);
        s = fmaf(xv.z, rv.z, s);
        s = fmaf(xv.w, rv.w, s);
    }

    __shared__ float red[256];
    red[threadIdx.x] = s;
    __syncthreads();
    for (int off = 128; off > 0; off >>= 1) {
        if (threadIdx.x < off) red[threadIdx.x] += red[threadIdx.x + off];
        __syncthreads();
    }
    if (threadIdx.x == 0) out[bc] = red[0] * (1.0f / (float)NN);
}

// ---------------------------------------------------------------------------
extern "C" void kernel_launch(void* const* d_in, const int* in_sizes, int n_in,
                              void* d_out, int out_size) {
    const float* x  = (const float*)d_in[0];   // [16, 512, 48, 48]
    const float* wq = (const float*)d_in[1];   // [512]
    float* out = (float*)d_out;                // [16, 512, 1, 1]

    prep_kernel<<<BB * (NN / 64), 256>>>(x, wq);
    gemm_kernel<<<dim3(NPAIRS, BB), 256>>>();
    out_kernel<<<BB * CC, 256>>>(x, out);
}

// round 9
// speedup vs baseline: 4.0333x; 1.4120x over previous
#include <cuda_runtime.h>
#include <cuda_fp16.h>
#include <math.h>
#include <stdint.h>

#define BB 16
#define CC 512
#define NN 2304
#define NT 18            // NN / 128 tiles
#define NPAIRS 171       // NT*(NT+1)/2

// ---------------- scratch (__device__ globals; no allocs allowed) -----------
__device__ __half g_xn[(size_t)BB * CC * NN];   // fp16-RN normalized x, [b][c][n]
__device__ float g_att[BB * NN];
__device__ float g_refine[BB * NN];

__device__ __forceinline__ uint32_t smem_u32(const void* p) {
    uint32_t a;
    asm("{ .reg .u64 t; cvta.to.shared.u64 t, %1; cvt.u32.u64 %0, t; }" : "=r"(a) : "l"(p));
    return a;
}
__device__ __forceinline__ void cp_async16(uint32_t dst, const void* src) {
    asm volatile("cp.async.cg.shared.global [%0], [%1], 16;" :: "r"(dst), "l"(src) : "memory");
}
#define CP_COMMIT() asm volatile("cp.async.commit_group;" ::: "memory")

__device__ __forceinline__ void mma_f16(float c[4], const uint32_t a[4], const uint32_t b[2]) {
    asm("mma.sync.aligned.m16n8k16.row.col.f32.f16.f16.f32 "
        "{%0,%1,%2,%3}, {%4,%5,%6,%7}, {%8,%9}, {%0,%1,%2,%3};"
        : "+f"(c[0]), "+f"(c[1]), "+f"(c[2]), "+f"(c[3])
        : "r"(a[0]), "r"(a[1]), "r"(a[2]), "r"(a[3]), "r"(b[0]), "r"(b[1]));
}

#define LDSM_X4_T(r0, r1, r2, r3, addr) \
    asm volatile("ldmatrix.sync.aligned.m8n8.x4.trans.shared.b16 {%0,%1,%2,%3}, [%4];" \
        : "=r"(r0), "=r"(r1), "=r"(r2), "=r"(r3) : "r"(addr))

// ---------------------------------------------------------------------------
// prep (R7 shape): per (b,n): ss & dot -> att, inv; second cache-hot pass
// writes g_xn[b][c][n] = rn_f16(x * inv). grid = BB * NN/64 = 576
// ---------------------------------------------------------------------------
__global__ void __launch_bounds__(256) prep_kernel(const float* __restrict__ x,
                                                   const float* __restrict__ wq) {
    __shared__ float swq[CC];
    __shared__ float s_ss[256], s_dot[256];
    __shared__ float s_inv[64];

    int tid = threadIdx.x;
    for (int i = tid; i < CC; i += 256) swq[i] = wq[i];
    __syncthreads();

    int b  = blockIdx.x / (NN / 64);
    int nt = blockIdx.x % (NN / 64);
    int cs = tid >> 6;          // c-slice 0..3
    int nl = tid & 63;
    int n  = nt * 64 + nl;

    const float* xb = x + ((size_t)b * CC + cs * 128) * NN + n;
    const float* wp = swq + cs * 128;

    float ss = 0.f, dot = 0.f;
    #pragma unroll 8
    for (int c = 0; c < 128; c++) {
        float v = xb[(size_t)c * NN];
        ss  = fmaf(v, v, ss);
        dot = fmaf(v, wp[c], dot);
    }
    s_ss[tid] = ss; s_dot[tid] = dot;
    __syncthreads();

    if (tid < 64) {
        float tss = s_ss[tid] + s_ss[tid + 64] + s_ss[tid + 128] + s_ss[tid + 192];
        float td  = s_dot[tid] + s_dot[tid + 64] + s_dot[tid + 128] + s_dot[tid + 192];
        s_inv[tid] = 1.0f / fmaxf(sqrtf(tss), 1e-12f);
        int gid = b * NN + nt * 64 + tid;
        g_att[gid]    = (td > 20.0f) ? td : log1pf(expf(td));
        g_refine[gid] = 0.0f;
    }
    __syncthreads();

    float inv = s_inv[nl];
    __half* ob = g_xn + ((size_t)b * CC + cs * 128) * NN + n;
    #pragma unroll 8
    for (int c = 0; c < 128; c++) {
        float v = xb[(size_t)c * NN];
        ob[(size_t)c * NN] = __float2half_rn(v * inv);
    }
}

// ---------------------------------------------------------------------------
// gemm: per (b, tile-pair i<=j): S = Xn_i^T Xn_j over K=512 (fp16 mma.sync)
// smem tiles [k][n], row stride 136 halves (272B -> conflict-free ldmatrix).
// fragments via ldmatrix.x4.trans.
// ---------------------------------------------------------------------------
#define BK 32
#define ROWH 136                   // halves per smem row (128 + 8 pad)

__global__ void __launch_bounds__(256) gemm_kernel() {
    __shared__ __half As[2][BK][ROWH];   // 17408 B
    __shared__ __half Bs[2][BK][ROWH];   // 17408 B
    __shared__ float srow[128], scol[128];
    __shared__ float attR[128], attQ[128];

    int b    = blockIdx.y;
    int pair = blockIdx.x;
    int i = 0, rem = pair;
    while (rem >= NT - i) { rem -= NT - i; i++; }
    int j = i + rem;
    int rblk = i * 128;
    int qblk = j * 128;
    bool diag = (i == j);

    int tid  = threadIdx.x;
    int lane = tid & 31;
    int wid  = tid >> 5;
    int warpR = (wid >> 1) * 32;  // 4 warp-rows
    int warpQ = (wid & 1) * 64;   // 2 warp-cols

    if (tid < 128) {
        attR[tid] = g_att[b * NN + rblk + tid];
        attQ[tid] = g_att[b * NN + qblk + tid];
        srow[tid] = 0.f; scol[tid] = 0.f;
    }

    const __half* xb = g_xn + (size_t)b * CC * NN;
    uint32_t as_base = smem_u32(&As[0][0][0]);
    uint32_t bs_base = smem_u32(&Bs[0][0][0]);

    // stage load: 2 tiles x 32 k-rows x 16 granules(16B) = 1024 granules
    auto load_stage = [&](int round, int stg) {
        int kof = round * BK;
        #pragma unroll
        for (int it = 0; it < 4; it++) {
            int g = tid + it * 256;
            int tsel = g >> 9;            // 0 = A, 1 = B
            int r    = (g >> 4) & 31;     // k row
            int c16  = g & 15;            // 16B granule (8 halves)
            const __half* src = xb + (size_t)(kof + r) * NN +
                                (tsel ? qblk : rblk) + c16 * 8;
            uint32_t dst = (tsel ? bs_base : as_base) +
                           (uint32_t)stg * (BK * ROWH * 2) + r * (ROWH * 2) + c16 * 16;
            cp_async16(dst, src);
        }
        CP_COMMIT();
    };

    float acc[2][8][4];
    #pragma unroll
    for (int mi = 0; mi < 2; mi++)
        #pragma unroll
        for (int ni = 0; ni < 8; ni++)
            #pragma unroll
            for (int k = 0; k < 4; k++) acc[mi][ni][k] = 0.f;

    // per-lane ldmatrix address components (byte offsets within a k-slice)
    int l8 = lane & 7;
    int a_k = l8 + ((lane >> 4) & 1) * 8;           // k within 16
    int a_m = ((lane >> 3) & 1) * 8;                // +8 m for groups 1,3
    int b_k = l8 + ((lane >> 3) & 1) * 8;
    int b_n = ((lane >> 4) & 1) * 8;

    uint32_t a_off0 = (uint32_t)(a_k * ROWH + warpR + a_m) * 2;
    uint32_t a_off1 = a_off0 + 16 * 2;              // mi=1: +16 m
    uint32_t b_off[4];
    #pragma unroll
    for (int q = 0; q < 4; q++)
        b_off[q] = (uint32_t)(b_k * ROWH + warpQ + q * 16 + b_n) * 2;

    load_stage(0, 0);

    const int ROUNDS = CC / BK;   // 16
    int tg = lane & 3;
    int gp = lane >> 2;

    for (int kb = 0; kb < ROUNDS; kb++) {
        int cs = kb & 1;
        if (kb + 1 < ROUNDS) {
            load_stage(kb + 1, (kb + 1) & 1);
            asm volatile("cp.async.wait_group 1;" ::: "memory");
        } else {
            asm volatile("cp.async.wait_group 0;" ::: "memory");
        }
        __syncthreads();

        uint32_t stage_a = as_base + (uint32_t)cs * (BK * ROWH * 2);
        uint32_t stage_b = bs_base + (uint32_t)cs * (BK * ROWH * 2);

        #pragma unroll
        for (int ks = 0; ks < BK; ks += 16) {
            uint32_t krow = (uint32_t)ks * (ROWH * 2);
            uint32_t afr[2][4], bfr[8][2];
            LDSM_X4_T(afr[0][0], afr[0][1], afr[0][2], afr[0][3], stage_a + krow + a_off0);
            LDSM_X4_T(afr[1][0], afr[1][1], afr[1][2], afr[1][3], stage_a + krow + a_off1);
            #pragma unroll
            for (int q = 0; q < 4; q++)
                LDSM_X4_T(bfr[2 * q][0], bfr[2 * q][1], bfr[2 * q + 1][0], bfr[2 * q + 1][1],
                          stage_b + krow + b_off[q]);
            #pragma unroll
            for (int mi = 0; mi < 2; mi++)
                #pragma unroll
                for (int ni = 0; ni < 8; ni++)
                    mma_f16(acc[mi][ni], afr[mi], bfr[ni]);
        }
        __syncthreads();
    }

    // ----- epilogue -----
    float csum[8][2];
    #pragma unroll
    for (int ni = 0; ni < 8; ni++) { csum[ni][0] = 0.f; csum[ni][1] = 0.f; }

    #pragma unroll
    for (int mi = 0; mi < 2; mi++) {
        int r0 = warpR + mi * 16 + gp;
        int r1 = r0 + 8;
        float ar0 = attR[r0], ar1 = attR[r1];
        float rlo = 0.f, rhi = 0.f;
        #pragma unroll
        for (int ni = 0; ni < 8; ni++) {
            int c0 = warpQ + ni * 8 + tg * 2;
            int c1 = c0 + 1;
            float aq0 = attQ[c0], aq1 = attQ[c1];
            float s, p;
            s = fmaxf(acc[mi][ni][0], 0.f); p = s * s;
            rlo = fmaf(p, aq0, rlo); csum[ni][0] = fmaf(p, ar0, csum[ni][0]);
            s = fmaxf(acc[mi][ni][1], 0.f); p = s * s;
            rlo = fmaf(p, aq1, rlo); csum[ni][1] = fmaf(p, ar0, csum[ni][1]);
            s = fmaxf(acc[mi][ni][2], 0.f); p = s * s;
            rhi = fmaf(p, aq0, rhi); csum[ni][0] = fmaf(p, ar1, csum[ni][0]);
            s = fmaxf(acc[mi][ni][3], 0.f); p = s * s;
            rhi = fmaf(p, aq1, rhi); csum[ni][1] = fmaf(p, ar1, csum[ni][1]);
        }
        rlo += __shfl_xor_sync(0xffffffffu, rlo, 1);
        rlo += __shfl_xor_sync(0xffffffffu, rlo, 2);
        rhi += __shfl_xor_sync(0xffffffffu, rhi, 1);
        rhi += __shfl_xor_sync(0xffffffffu, rhi, 2);
        if (tg == 0) {
            atomicAdd(&srow[r0], rlo);
            atomicAdd(&srow[r1], rhi);
        }
    }
    if (!diag) {
        #pragma unroll
        for (int ni = 0; ni < 8; ni++) {
            float c0v = csum[ni][0], c1v = csum[ni][1];
            c0v += __shfl_xor_sync(0xffffffffu, c0v, 4);
            c0v += __shfl_xor_sync(0xffffffffu, c0v, 8);
            c0v += __shfl_xor_sync(0xffffffffu, c0v, 16);
            c1v += __shfl_xor_sync(0xffffffffu, c1v, 4);
            c1v += __shfl_xor_sync(0xffffffffu, c1v, 8);
            c1v += __shfl_xor_sync(0xffffffffu, c1v, 16);
            if (gp == 0) {
                int c0 = warpQ + ni * 8 + tg * 2;
                atomicAdd(&scol[c0],     c0v);
                atomicAdd(&scol[c0 + 1], c1v);
            }
        }
    }
    __syncthreads();

    if (tid < 128) {
        atomicAdd(&g_refine[b * NN + rblk + tid], srow[tid]);
        if (!diag) atomicAdd(&g_refine[b * NN + qblk + tid], scol[tid]);
    }
}

// ---------------------------------------------------------------------------
// out: out[b][c] = mean_n x[b][c][n] * refine[b][n]
// ---------------------------------------------------------------------------
__global__ void __launch_bounds__(256) out_kernel(const float* __restrict__ x,
                                                  float* __restrict__ out) {
    int bc = blockIdx.x;
    int b = bc / CC;
    const float4* xr = (const float4*)(x + (size_t)bc * NN);
    const float4* rf = (const float4*)(g_refine + b * NN);

    float s = 0.f;
    for (int q = threadIdx.x; q < NN / 4; q += 256) {
        float4 xv = xr[q];
        float4 rv = rf[q];
        s = fmaf(xv.x, rv.x, s);
        s = fmaf(xv.y, rv.y, s);
        s = fmaf(xv.z, rv.z, s);
        s = fmaf(xv.w, rv.w, s);
    }

    __shared__ float red[256];
    red[threadIdx.x] = s;
    __syncthreads();
    for (int off = 128; off > 0; off >>= 1) {
        if (threadIdx.x < off) red[threadIdx.x] += red[threadIdx.x + off];
        __syncthreads();
    }
    if (threadIdx.x == 0) out[bc] = red[0] * (1.0f / (float)NN);
}

// ---------------------------------------------------------------------------
extern "C" void kernel_launch(void* const* d_in, const int* in_sizes, int n_in,
                              void* d_out, int out_size) {
    const float* x  = (const float*)d_in[0];   // [16, 512, 48, 48]
    const float* wq = (const float*)d_in[1];   // [512]
    float* out = (float*)d_out;                // [16, 512, 1, 1]

    prep_kernel<<<BB * (NN / 64), 256>>>(x, wq);
    gemm_kernel<<<dim3(NPAIRS, BB), 256>>>();
    out_kernel<<<BB * CC, 256>>>(x, out);
}

// round 10
// speedup vs baseline: 4.3542x; 1.0796x over previous
#include <cuda_runtime.h>
#include <cuda_fp16.h>
#include <math.h>
#include <stdint.h>

#define BB 16
#define CC 512
#define NN 2304
#define NT 18            // NN / 128 tiles
#define NPAIRS 171       // NT*(NT+1)/2

// ---------------- scratch (__device__ globals; no allocs allowed) -----------
__device__ __half g_xn[(size_t)BB * CC * NN];   // fp16-RN normalized x, [b][c][n]
__device__ float g_att[BB * NN];
__device__ float g_refine[BB * NN];

__device__ __forceinline__ uint32_t smem_u32(const void* p) {
    uint32_t a;
    asm("{ .reg .u64 t; cvta.to.shared.u64 t, %1; cvt.u32.u64 %0, t; }" : "=r"(a) : "l"(p));
    return a;
}
__device__ __forceinline__ void cp_async16(uint32_t dst, const void* src) {
    asm volatile("cp.async.cg.shared.global [%0], [%1], 16;" :: "r"(dst), "l"(src) : "memory");
}
#define CP_COMMIT() asm volatile("cp.async.commit_group;" ::: "memory")

__device__ __forceinline__ void mma_f16(float c[4], const uint32_t a[4], const uint32_t b[2]) {
    asm("mma.sync.aligned.m16n8k16.row.col.f32.f16.f16.f32 "
        "{%0,%1,%2,%3}, {%4,%5,%6,%7}, {%8,%9}, {%0,%1,%2,%3};"
        : "+f"(c[0]), "+f"(c[1]), "+f"(c[2]), "+f"(c[3])
        : "r"(a[0]), "r"(a[1]), "r"(a[2]), "r"(a[3]), "r"(b[0]), "r"(b[1]));
}

#define LDSM_X4_T(r0, r1, r2, r3, addr) \
    asm volatile("ldmatrix.sync.aligned.m8n8.x4.trans.shared.b16 {%0,%1,%2,%3}, [%4];" \
        : "=r"(r0), "=r"(r1), "=r"(r2), "=r"(r3) : "r"(addr))

// ---------------------------------------------------------------------------
// prep: block = 32 n x 8 c-slices (64 c each). Phase1 ss/dot -> inv, att;
// phase2 cache-hot re-read writes g_xn fp16. grid = BB * NN/32 = 1152
// ---------------------------------------------------------------------------
__global__ void __launch_bounds__(256) prep_kernel(const float* __restrict__ x,
                                                   const float* __restrict__ wq) {
    __shared__ float swq[CC];
    __shared__ float s_ss[256], s_dot[256];
    __shared__ float s_inv[32];

    int tid = threadIdx.x;
    for (int i = tid; i < CC; i += 256) swq[i] = wq[i];
    __syncthreads();

    int b  = blockIdx.x / (NN / 32);
    int nt = blockIdx.x % (NN / 32);
    int cs = tid >> 5;          // c-slice 0..7 (64 c each)
    int nl = tid & 31;
    int n  = nt * 32 + nl;

    const float* xb = x + ((size_t)b * CC + cs * 64) * NN + n;
    const float* wp = swq + cs * 64;

    float ss = 0.f, dot = 0.f;
    #pragma unroll 16
    for (int c = 0; c < 64; c++) {
        float v = xb[(size_t)c * NN];
        ss  = fmaf(v, v, ss);
        dot = fmaf(v, wp[c], dot);
    }
    s_ss[tid] = ss; s_dot[tid] = dot;
    __syncthreads();

    if (tid < 32) {
        float tss = 0.f, td = 0.f;
        #pragma unroll
        for (int k = 0; k < 8; k++) {
            tss += s_ss[tid + 32 * k];
            td  += s_dot[tid + 32 * k];
        }
        s_inv[tid] = 1.0f / fmaxf(sqrtf(tss), 1e-12f);
        int gid = b * NN + nt * 32 + tid;
        g_att[gid]    = (td > 20.0f) ? td : log1pf(expf(td));
        g_refine[gid] = 0.0f;
    }
    __syncthreads();

    float inv = s_inv[nl];
    __half* ob = g_xn + ((size_t)b * CC + cs * 64) * NN + n;
    #pragma unroll 16
    for (int c = 0; c < 64; c++) {
        float v = xb[(size_t)c * NN];
        ob[(size_t)c * NN] = __float2half_rn(v * inv);
    }
}

// ---------------------------------------------------------------------------
// gemm: per (b, tile-pair i<=j): S = Xn_i^T Xn_j over K=512 (fp16 mma.sync)
// smem tiles [k][n], row stride 136 halves; ldmatrix.x4.trans fragments.
// 3-stage cp.async pipeline, one __syncthreads per round. Dynamic smem.
// ---------------------------------------------------------------------------
#define BK 32
#define ROWH 136                         // halves per smem row (128 + 8 pad)
#define TSTRIDE (BK * ROWH * 2)          // bytes per tile-stage: 8704
#define BS_OFF  (3 * TSTRIDE)            // B tiles after 3 A stages: 26112
#define AUX_OFF (6 * TSTRIDE)            // 52224
#define GEMM_SMEM (AUX_OFF + 4 * 128 * 4)  // + attR/attQ/srow/scol = 54272

__global__ void __launch_bounds__(256) gemm_kernel() {
    extern __shared__ char sm[];
    float* attR = (float*)(sm + AUX_OFF);
    float* attQ = attR + 128;
    float* srow = attQ + 128;
    float* scol = srow + 128;

    int b    = blockIdx.y;
    int pair = blockIdx.x;
    int i = 0, rem = pair;
    while (rem >= NT - i) { rem -= NT - i; i++; }
    int j = i + rem;
    int rblk = i * 128;
    int qblk = j * 128;
    bool diag = (i == j);

    int tid  = threadIdx.x;
    int lane = tid & 31;
    int wid  = tid >> 5;
    int warpR = (wid >> 1) * 32;  // 4 warp-rows
    int warpQ = (wid & 1) * 64;   // 2 warp-cols

    if (tid < 128) {
        attR[tid] = g_att[b * NN + rblk + tid];
        attQ[tid] = g_att[b * NN + qblk + tid];
        srow[tid] = 0.f; scol[tid] = 0.f;
    }

    const __half* xb = g_xn + (size_t)b * CC * NN;
    uint32_t as_base = smem_u32(sm);
    uint32_t bs_base = as_base + BS_OFF;

    // stage load: 2 tiles x 32 k-rows x 16 granules(16B) = 1024 granules
    auto load_stage = [&](int round, int stg) {
        int kof = round * BK;
        #pragma unroll
        for (int it = 0; it < 4; it++) {
            int g = tid + it * 256;
            int tsel = g >> 9;            // 0 = A, 1 = B
            int r    = (g >> 4) & 31;     // k row
            int c16  = g & 15;            // 16B granule (8 halves)
            const __half* src = xb + (size_t)(kof + r) * NN +
                                (tsel ? qblk : rblk) + c16 * 8;
            uint32_t dst = (tsel ? bs_base : as_base) +
                           (uint32_t)stg * TSTRIDE + r * (ROWH * 2) + c16 * 16;
            cp_async16(dst, src);
        }
        CP_COMMIT();
    };

    float acc[2][8][4];
    #pragma unroll
    for (int mi = 0; mi < 2; mi++)
        #pragma unroll
        for (int ni = 0; ni < 8; ni++)
            #pragma unroll
            for (int k = 0; k < 4; k++) acc[mi][ni][k] = 0.f;

    // per-lane ldmatrix address components
    int l8 = lane & 7;
    int a_k = l8 + ((lane >> 4) & 1) * 8;
    int a_m = ((lane >> 3) & 1) * 8;
    int b_k = l8 + ((lane >> 3) & 1) * 8;
    int b_n = ((lane >> 4) & 1) * 8;

    uint32_t a_off0 = (uint32_t)(a_k * ROWH + warpR + a_m) * 2;
    uint32_t a_off1 = a_off0 + 16 * 2;
    uint32_t b_off[4];
    #pragma unroll
    for (int q = 0; q < 4; q++)
        b_off[q] = (uint32_t)(b_k * ROWH + warpQ + q * 16 + b_n) * 2;

    load_stage(0, 0);
    load_stage(1, 1);

    const int ROUNDS = CC / BK;   // 16
    int tg = lane & 3;
    int gp = lane >> 2;

    for (int kb = 0; kb < ROUNDS; kb++) {
        int cs = kb % 3;
        if (kb < ROUNDS - 1) asm volatile("cp.async.wait_group 1;" ::: "memory");
        else                 asm volatile("cp.async.wait_group 0;" ::: "memory");
        __syncthreads();

        if (kb + 2 < ROUNDS) load_stage(kb + 2, (kb + 2) % 3);

        uint32_t stage_a = as_base + (uint32_t)cs * TSTRIDE;
        uint32_t stage_b = bs_base + (uint32_t)cs * TSTRIDE;

        #pragma unroll
        for (int ks = 0; ks < BK; ks += 16) {
            uint32_t krow = (uint32_t)ks * (ROWH * 2);
            uint32_t afr[2][4], bfr[8][2];
            LDSM_X4_T(afr[0][0], afr[0][1], afr[0][2], afr[0][3], stage_a + krow + a_off0);
            LDSM_X4_T(afr[1][0], afr[1][1], afr[1][2], afr[1][3], stage_a + krow + a_off1);
            #pragma unroll
            for (int q = 0; q < 4; q++)
                LDSM_X4_T(bfr[2 * q][0], bfr[2 * q][1], bfr[2 * q + 1][0], bfr[2 * q + 1][1],
                          stage_b + krow + b_off[q]);
            #pragma unroll
            for (int mi = 0; mi < 2; mi++)
                #pragma unroll
                for (int ni = 0; ni < 8; ni++)
                    mma_f16(acc[mi][ni], afr[mi], bfr[ni]);
        }
    }
    __syncthreads();

    // ----- epilogue -----
    float csum[8][2];
    #pragma unroll
    for (int ni = 0; ni < 8; ni++) { csum[ni][0] = 0.f; csum[ni][1] = 0.f; }

    #pragma unroll
    for (int mi = 0; mi < 2; mi++) {
        int r0 = warpR + mi * 16 + gp;
        int r1 = r0 + 8;
        float ar0 = attR[r0], ar1 = attR[r1];
        float rlo = 0.f, rhi = 0.f;
        #pragma unroll
        for (int ni = 0; ni < 8; ni++) {
            int c0 = warpQ + ni * 8 + tg * 2;
            int c1 = c0 + 1;
            float aq0 = attQ[c0], aq1 = attQ[c1];
            float s, p;
            s = fmaxf(acc[mi][ni][0], 0.f); p = s * s;
            rlo = fmaf(p, aq0, rlo); csum[ni][0] = fmaf(p, ar0, csum[ni][0]);
            s = fmaxf(acc[mi][ni][1], 0.f); p = s * s;
            rlo = fmaf(p, aq1, rlo); csum[ni][1] = fmaf(p, ar0, csum[ni][1]);
            s = fmaxf(acc[mi][ni][2], 0.f); p = s * s;
            rhi = fmaf(p, aq0, rhi); csum[ni][0] = fmaf(p, ar1, csum[ni][0]);
            s = fmaxf(acc[mi][ni][3], 0.f); p = s * s;
            rhi = fmaf(p, aq1, rhi); csum[ni][1] = fmaf(p, ar1, csum[ni][1]);
        }
        rlo += __shfl_xor_sync(0xffffffffu, rlo, 1);
        rlo += __shfl_xor_sync(0xffffffffu, rlo, 2);
        rhi += __shfl_xor_sync(0xffffffffu, rhi, 1);
        rhi += __shfl_xor_sync(0xffffffffu, rhi, 2);
        if (tg == 0) {
            atomicAdd(&srow[r0], rlo);
            atomicAdd(&srow[r1], rhi);
        }
    }
    if (!diag) {
        #pragma unroll
        for (int ni = 0; ni < 8; ni++) {
            float c0v = csum[ni][0], c1v = csum[ni][1];
            c0v += __shfl_xor_sync(0xffffffffu, c0v, 4);
            c0v += __shfl_xor_sync(0xffffffffu, c0v, 8);
            c0v += __shfl_xor_sync(0xffffffffu, c0v, 16);
            c1v += __shfl_xor_sync(0xffffffffu, c1v, 4);
            c1v += __shfl_xor_sync(0xffffffffu, c1v, 8);
            c1v += __shfl_xor_sync(0xffffffffu, c1v, 16);
            if (gp == 0) {
                int c0 = warpQ + ni * 8 + tg * 2;
                atomicAdd(&scol[c0],     c0v);
                atomicAdd(&scol[c0 + 1], c1v);
            }
        }
    }
    __syncthreads();

    if (tid < 128) {
        atomicAdd(&g_refine[b * NN + rblk + tid], srow[tid]);
        if (!diag) atomicAdd(&g_refine[b * NN + qblk + tid], scol[tid]);
    }
}

// ---------------------------------------------------------------------------
// out: warp per (b,c): out[b][c] = mean_n x[b][c][n] * refine[b][n]
// grid = BB*CC/8 = 1024, block 256 (8 warps)
// ---------------------------------------------------------------------------
__global__ void __launch_bounds__(256) out_kernel(const float* __restrict__ x,
                                                  float* __restrict__ out) {
    int wid  = threadIdx.x >> 5;
    int lane = threadIdx.x & 31;
    int bc = blockIdx.x * 8 + wid;
    int b = bc >> 9;

    const float4* xr = (const float4*)(x + (size_t)bc * NN);
    const float4* rf = (const float4*)(g_refine + b * NN);

    float s = 0.f;
    #pragma unroll 6
    for (int k = 0; k < 18; k++) {
        int q = lane + k * 32;
        float4 xv = __ldg(&xr[q]);
        float4 rv = rf[q];
        s = fmaf(xv.x, rv.x, s);
        s = fmaf(xv.y, rv.y, s);
        s = fmaf(xv.z, rv.z, s);
        s = fmaf(xv.w, rv.w, s);
    }
    #pragma unroll
    for (int off = 16; off > 0; off >>= 1)
        s += __shfl_xor_sync(0xffffffffu, s, off);
    if (lane == 0) out[bc] = s * (1.0f / (float)NN);
}

// ---------------------------------------------------------------------------
extern "C" void kernel_launch(void* const* d_in, const int* in_sizes, int n_in,
                              void* d_out, int out_size) {
    const float* x  = (const float*)d_in[0];   // [16, 512, 48, 48]
    const float* wq = (const float*)d_in[1];   // [512]
    float* out = (float*)d_out;                // [16, 512, 1, 1]

    cudaFuncSetAttribute(gemm_kernel, cudaFuncAttributeMaxDynamicSharedMemorySize, GEMM_SMEM);

    prep_kernel<<<BB * (NN / 32), 256>>>(x, wq);
    gemm_kernel<<<dim3(NPAIRS, BB), 256, GEMM_SMEM>>>();
    out_kernel<<<(BB * CC) / 8, 256>>>(x, out);
}

// round 11
// speedup vs baseline: 4.4960x; 1.0326x over previous
#include <cuda_runtime.h>
#include <cuda_fp16.h>
#include <math.h>
#include <stdint.h>

#define BB 16
#define CC 512
#define NN 2304
#define NT 18            // NN / 128 tiles
#define NPAIRS 171       // NT*(NT+1)/2

// ---------------- scratch (__device__ globals; no allocs allowed) -----------
__device__ __half g_xn[(size_t)BB * CC * NN];   // fp16-RN normalized x, [b][c][n]
__device__ float g_att[BB * NN];
__device__ float g_refine[BB * NN];

__device__ __forceinline__ uint32_t smem_u32(const void* p) {
    uint32_t a;
    asm("{ .reg .u64 t; cvta.to.shared.u64 t, %1; cvt.u32.u64 %0, t; }" : "=r"(a) : "l"(p));
    return a;
}
__device__ __forceinline__ void cp_async16(uint32_t dst, const void* src) {
    asm volatile("cp.async.cg.shared.global [%0], [%1], 16;" :: "r"(dst), "l"(src) : "memory");
}
#define CP_COMMIT() asm volatile("cp.async.commit_group;" ::: "memory")

__device__ __forceinline__ void mma_f16(float c[4], const uint32_t a[4], const uint32_t b[2]) {
    asm("mma.sync.aligned.m16n8k16.row.col.f32.f16.f16.f32 "
        "{%0,%1,%2,%3}, {%4,%5,%6,%7}, {%8,%9}, {%0,%1,%2,%3};"
        : "+f"(c[0]), "+f"(c[1]), "+f"(c[2]), "+f"(c[3])
        : "r"(a[0]), "r"(a[1]), "r"(a[2]), "r"(a[3]), "r"(b[0]), "r"(b[1]));
}

#define LDSM_X4_T(r0, r1, r2, r3, addr) \
    asm volatile("ldmatrix.sync.aligned.m8n8.x4.trans.shared.b16 {%0,%1,%2,%3}, [%4];" \
        : "=r"(r0), "=r"(r1), "=r"(r2), "=r"(r3) : "r"(addr))

// ---------------------------------------------------------------------------
// prep: block = 32 n x 8 c-slices (64 c each). Phase1 ss/dot -> inv, att;
// phase2 cache-hot re-read writes g_xn fp16. grid = BB * NN/32 = 1152
// ---------------------------------------------------------------------------
__global__ void __launch_bounds__(256) prep_kernel(const float* __restrict__ x,
                                                   const float* __restrict__ wq) {
    __shared__ float swq[CC];
    __shared__ float s_ss[256], s_dot[256];
    __shared__ float s_inv[32];

    int tid = threadIdx.x;
    for (int i = tid; i < CC; i += 256) swq[i] = wq[i];
    __syncthreads();

    int b  = blockIdx.x / (NN / 32);
    int nt = blockIdx.x % (NN / 32);
    int cs = tid >> 5;          // c-slice 0..7 (64 c each)
    int nl = tid & 31;
    int n  = nt * 32 + nl;

    const float* xb = x + ((size_t)b * CC + cs * 64) * NN + n;
    const float* wp = swq + cs * 64;

    float ss = 0.f, dot = 0.f;
    #pragma unroll 16
    for (int c = 0; c < 64; c++) {
        float v = xb[(size_t)c * NN];
        ss  = fmaf(v, v, ss);
        dot = fmaf(v, wp[c], dot);
    }
    s_ss[tid] = ss; s_dot[tid] = dot;
    __syncthreads();

    if (tid < 32) {
        float tss = 0.f, td = 0.f;
        #pragma unroll
        for (int k = 0; k < 8; k++) {
            tss += s_ss[tid + 32 * k];
            td  += s_dot[tid + 32 * k];
        }
        s_inv[tid] = 1.0f / fmaxf(sqrtf(tss), 1e-12f);
        int gid = b * NN + nt * 32 + tid;
        g_att[gid]    = (td > 20.0f) ? td : log1pf(expf(td));
        g_refine[gid] = 0.0f;
    }
    __syncthreads();

    float inv = s_inv[nl];
    __half* ob = g_xn + ((size_t)b * CC + cs * 64) * NN + n;
    #pragma unroll 16
    for (int c = 0; c < 64; c++) {
        float v = xb[(size_t)c * NN];
        ob[(size_t)c * NN] = __float2half_rn(v * inv);
    }
}

// ---------------------------------------------------------------------------
// gemm: per (b, tile-pair i<=j): S = Xn_i^T Xn_j over K=512 (fp16 mma.sync)
// smem tiles [k][n], row stride 136 halves; ldmatrix.x4.trans fragments.
// BK=64, 3-stage cp.async pipeline -> 8 rounds, one __syncthreads per round.
// ---------------------------------------------------------------------------
#define BK 64
#define ROWH 136                         // halves per smem row (128 + 8 pad)
#define TSTRIDE (BK * ROWH * 2)          // bytes per tile-stage: 17408
#define BS_OFF  (3 * TSTRIDE)            // B tiles after 3 A stages: 52224
#define AUX_OFF (6 * TSTRIDE)            // 104448
#define GEMM_SMEM (AUX_OFF + 4 * 128 * 4)  // + attR/attQ/srow/scol = 106496

__global__ void __launch_bounds__(256) gemm_kernel() {
    extern __shared__ char sm[];
    float* attR = (float*)(sm + AUX_OFF);
    float* attQ = attR + 128;
    float* srow = attQ + 128;
    float* scol = srow + 128;

    int b    = blockIdx.y;
    int pair = blockIdx.x;
    int i = 0, rem = pair;
    while (rem >= NT - i) { rem -= NT - i; i++; }
    int j = i + rem;
    int rblk = i * 128;
    int qblk = j * 128;
    bool diag = (i == j);

    int tid  = threadIdx.x;
    int lane = tid & 31;
    int wid  = tid >> 5;
    int warpR = (wid >> 1) * 32;  // 4 warp-rows
    int warpQ = (wid & 1) * 64;   // 2 warp-cols

    if (tid < 128) {
        attR[tid] = g_att[b * NN + rblk + tid];
        attQ[tid] = g_att[b * NN + qblk + tid];
        srow[tid] = 0.f; scol[tid] = 0.f;
    }

    const __half* xb = g_xn + (size_t)b * CC * NN;
    uint32_t as_base = smem_u32(sm);
    uint32_t bs_base = as_base + BS_OFF;

    // stage load: 2 tiles x 64 k-rows x 16 granules(16B) = 2048 granules, 8/thread
    auto load_stage = [&](int round, int stg) {
        int kof = round * BK;
        #pragma unroll
        for (int it = 0; it < 8; it++) {
            int g = tid + it * 256;
            int tsel = g >> 10;           // 0 = A, 1 = B
            int r    = (g >> 4) & 63;     // k row
            int c16  = g & 15;            // 16B granule (8 halves)
            const __half* src = xb + (size_t)(kof + r) * NN +
                                (tsel ? qblk : rblk) + c16 * 8;
            uint32_t dst = (tsel ? bs_base : as_base) +
                           (uint32_t)stg * TSTRIDE + r * (ROWH * 2) + c16 * 16;
            cp_async16(dst, src);
        }
        CP_COMMIT();
    };

    float acc[2][8][4];
    #pragma unroll
    for (int mi = 0; mi < 2; mi++)
        #pragma unroll
        for (int ni = 0; ni < 8; ni++)
            #pragma unroll
            for (int k = 0; k < 4; k++) acc[mi][ni][k] = 0.f;

    // per-lane ldmatrix address components
    int l8 = lane & 7;
    int a_k = l8 + ((lane >> 4) & 1) * 8;
    int a_m = ((lane >> 3) & 1) * 8;
    int b_k = l8 + ((lane >> 3) & 1) * 8;
    int b_n = ((lane >> 4) & 1) * 8;

    uint32_t a_off0 = (uint32_t)(a_k * ROWH + warpR + a_m) * 2;
    uint32_t a_off1 = a_off0 + 16 * 2;
    uint32_t b_off[4];
    #pragma unroll
    for (int q = 0; q < 4; q++)
        b_off[q] = (uint32_t)(b_k * ROWH + warpQ + q * 16 + b_n) * 2;

    load_stage(0, 0);
    load_stage(1, 1);

    const int ROUNDS = CC / BK;   // 8
    int tg = lane & 3;
    int gp = lane >> 2;

    for (int kb = 0; kb < ROUNDS; kb++) {
        int cs = kb % 3;
        if (kb < ROUNDS - 1) asm volatile("cp.async.wait_group 1;" ::: "memory");
        else                 asm volatile("cp.async.wait_group 0;" ::: "memory");
        __syncthreads();

        if (kb + 2 < ROUNDS) load_stage(kb + 2, (kb + 2) % 3);

        uint32_t stage_a = as_base + (uint32_t)cs * TSTRIDE;
        uint32_t stage_b = bs_base + (uint32_t)cs * TSTRIDE;

        #pragma unroll
        for (int ks = 0; ks < BK; ks += 16) {
            uint32_t krow = (uint32_t)ks * (ROWH * 2);
            uint32_t afr[2][4], bfr[8][2];
            LDSM_X4_T(afr[0][0], afr[0][1], afr[0][2], afr[0][3], stage_a + krow + a_off0);
            LDSM_X4_T(afr[1][0], afr[1][1], afr[1][2], afr[1][3], stage_a + krow + a_off1);
            #pragma unroll
            for (int q = 0; q < 4; q++)
                LDSM_X4_T(bfr[2 * q][0], bfr[2 * q][1], bfr[2 * q + 1][0], bfr[2 * q + 1][1],
                          stage_b + krow + b_off[q]);
            #pragma unroll
            for (int mi = 0; mi < 2; mi++)
                #pragma unroll
                for (int ni = 0; ni < 8; ni++)
                    mma_f16(acc[mi][ni], afr[mi], bfr[ni]);
        }
    }
    __syncthreads();

    // ----- epilogue -----
    float csum[8][2];
    #pragma unroll
    for (int ni = 0; ni < 8; ni++) { csum[ni][0] = 0.f; csum[ni][1] = 0.f; }

    #pragma unroll
    for (int mi = 0; mi < 2; mi++) {
        int r0 = warpR + mi * 16 + gp;
        int r1 = r0 + 8;
        float ar0 = attR[r0], ar1 = attR[r1];
        float rlo = 0.f, rhi = 0.f;
        #pragma unroll
        for (int ni = 0; ni < 8; ni++) {
            int c0 = warpQ + ni * 8 + tg * 2;
            int c1 = c0 + 1;
            float aq0 = attQ[c0], aq1 = attQ[c1];
            float s, p;
            s = fmaxf(acc[mi][ni][0], 0.f); p = s * s;
            rlo = fmaf(p, aq0, rlo); csum[ni][0] = fmaf(p, ar0, csum[ni][0]);
            s = fmaxf(acc[mi][ni][1], 0.f); p = s * s;
            rlo = fmaf(p, aq1, rlo); csum[ni][1] = fmaf(p, ar0, csum[ni][1]);
            s = fmaxf(acc[mi][ni][2], 0.f); p = s * s;
            rhi = fmaf(p, aq0, rhi); csum[ni][0] = fmaf(p, ar1, csum[ni][0]);
            s = fmaxf(acc[mi][ni][3], 0.f); p = s * s;
            rhi = fmaf(p, aq1, rhi); csum[ni][1] = fmaf(p, ar1, csum[ni][1]);
        }
        rlo += __shfl_xor_sync(0xffffffffu, rlo, 1);
        rlo += __shfl_xor_sync(0xffffffffu, rlo, 2);
        rhi += __shfl_xor_sync(0xffffffffu, rhi, 1);
        rhi += __shfl_xor_sync(0xffffffffu, rhi, 2);
        if (tg == 0) {
            atomicAdd(&srow[r0], rlo);
            atomicAdd(&srow[r1], rhi);
        }
    }
    if (!diag) {
        #pragma unroll
        for (int ni = 0; ni < 8; ni++) {
            float c0v = csum[ni][0], c1v = csum[ni][1];
            c0v += __shfl_xor_sync(0xffffffffu, c0v, 4);
            c0v += __shfl_xor_sync(0xffffffffu, c0v, 8);
            c0v += __shfl_xor_sync(0xffffffffu, c0v, 16);
            c1v += __shfl_xor_sync(0xffffffffu, c1v, 4);
            c1v += __shfl_xor_sync(0xffffffffu, c1v, 8);
            c1v += __shfl_xor_sync(0xffffffffu, c1v, 16);
            if (gp == 0) {
                int c0 = warpQ + ni * 8 + tg * 2;
                atomicAdd(&scol[c0],     c0v);
                atomicAdd(&scol[c0 + 1], c1v);
            }
        }
    }
    __syncthreads();

    if (tid < 128) {
        atomicAdd(&g_refine[b * NN + rblk + tid], srow[tid]);
        if (!diag) atomicAdd(&g_refine[b * NN + qblk + tid], scol[tid]);
    }
}

// ---------------------------------------------------------------------------
// out: warp per (b,c): out[b][c] = mean_n x[b][c][n] * refine[b][n]
// grid = BB*CC/8 = 1024, block 256 (8 warps)
// ---------------------------------------------------------------------------
__global__ void __launch_bounds__(256) out_kernel(const float* __restrict__ x,
                                                  float* __restrict__ out) {
    int wid  = threadIdx.x >> 5;
    int lane = threadIdx.x & 31;
    int bc = blockIdx.x * 8 + wid;
    int b = bc >> 9;

    const float4* xr = (const float4*)(x + (size_t)bc * NN);
    const float4* rf = (const float4*)(g_refine + b * NN);

    float s = 0.f;
    #pragma unroll 6
    for (int k = 0; k < 18; k++) {
        int q = lane + k * 32;
        float4 xv = __ldg(&xr[q]);
        float4 rv = rf[q];
        s = fmaf(xv.x, rv.x, s);
        s = fmaf(xv.y, rv.y, s);
        s = fmaf(xv.z, rv.z, s);
        s = fmaf(xv.w, rv.w, s);
    }
    #pragma unroll
    for (int off = 16; off > 0; off >>= 1)
        s += __shfl_xor_sync(0xffffffffu, s, off);
    if (lane == 0) out[bc] = s * (1.0f / (float)NN);
}

// ---------------------------------------------------------------------------
extern "C" void kernel_launch(void* const* d_in, const int* in_sizes, int n_in,
                              void* d_out, int out_size) {
    const float* x  = (const float*)d_in[0];   // [16, 512, 48, 48]
    const float* wq = (const float*)d_in[1];   // [512]
    float* out = (float*)d_out;                // [16, 512, 1, 1]

    cudaFuncSetAttribute(gemm_kernel, cudaFuncAttributeMaxDynamicSharedMemorySize, GEMM_SMEM);

    prep_kernel<<<BB * (NN / 32), 256>>>(x, wq);
    gemm_kernel<<<dim3(NPAIRS, BB), 256, GEMM_SMEM>>>();
    out_kernel<<<(BB * CC) / 8, 256>>>(x, out);
}